// round 10
// baseline (speedup 1.0000x reference)
#include <cuda_runtime.h>
#include <math.h>

#define N_PTS   131072
#define N_FEATS 1000
#define FDIM    64
#define YSTR    104        // padded scratch row stride (100 valid + 4 pad)
#define CF      250        // feature-vector chunk rows staged in smem (80KB total -> 2 blocks/SM)
#define HID     128
#define WS      132        // smem row stride (words), conflict-free float4 reads

// Scratch for [PE(36) | feats(64)] rows. __device__ global (no runtime alloc).
__device__ __align__(16) float g_y[(size_t)N_PTS * YSTR];

// ---------------------------------------------------------------------------
// Kernel 1: distance softmax over 1000 features + weighted feature gather + PE
// ---------------------------------------------------------------------------
__global__ void __launch_bounds__(256, 2) attn_kernel(
    const float* __restrict__ x,
    const float* __restrict__ floc,
    const float* __restrict__ fvec)
{
    extern __shared__ float sm[];
    float* Mx = sm;                   // [1000] = -2*loc.x
    float* My = sm + N_FEATS;         // [1000] = -2*loc.y
    float* Mz = sm + 2 * N_FEATS;     // [1000] = -2*loc.z
    float* Nn = sm + 3 * N_FEATS;     // [1000] = |loc|^2
    float* Vs = sm + 4 * N_FEATS;     // [CF*64]

    const int tid = threadIdx.x;
    const int p   = blockIdx.x * 256 + tid;

    // Stage locations (pre-scaled) + norms
    for (int i = tid; i < N_FEATS; i += 256) {
        float a = floc[3 * i + 0];
        float b = floc[3 * i + 1];
        float c = floc[3 * i + 2];
        Mx[i] = -2.0f * a; My[i] = -2.0f * b; Mz[i] = -2.0f * c;
        Nn[i] = a * a + b * b + c * c;
    }
    __syncthreads();

    const float x0 = x[3 * p + 0];
    const float x1 = x[3 * p + 1];
    const float x2 = x[3 * p + 2];
    const float xx = x0 * x0 + x1 * x1 + x2 * x2;

    // Pass 1: max of inv_d. inv = clamp(rsqrt(d2), 1e6) == 1/(sqrt(d2)+1e-6)
    // to within 1e-5 rel for any d2 of nonzero measure.
    float m = -1e30f;
    #pragma unroll 4
    for (int f = 0; f < N_FEATS; f++) {
        float d2 = fmaf(x2, Mz[f], fmaf(x1, My[f], fmaf(x0, Mx[f], xx + Nn[f])));
        d2 = fmaxf(d2, 0.0f);
        float inv = fminf(rsqrtf(d2), 1e6f);
        m = fmaxf(m, inv);
    }

    // Pass 2: exp weights + weighted V accumulation (64 regs)
    float s = 0.0f;
    float acc[FDIM];
    #pragma unroll
    for (int j = 0; j < FDIM; j++) acc[j] = 0.0f;

    for (int ch = 0; ch < N_FEATS / CF; ch++) {
        __syncthreads();
        const float4* src = (const float4*)(fvec + (size_t)ch * CF * FDIM);
        float4*       dst = (float4*)Vs;
        for (int i = tid; i < CF * FDIM / 4; i += 256) dst[i] = src[i];
        __syncthreads();

        const int base = ch * CF;
        #pragma unroll 1
        for (int f = 0; f < CF; f++) {
            const int g = base + f;
            float d2 = fmaf(x2, Mz[g], fmaf(x1, My[g], fmaf(x0, Mx[g], xx + Nn[g])));
            d2 = fmaxf(d2, 0.0f);
            float inv = fminf(rsqrtf(d2), 1e6f);
            float w = __expf(inv - m);
            s += w;
            const float4* vr = (const float4*)(Vs + f * FDIM);  // warp-broadcast
            #pragma unroll
            for (int q = 0; q < 16; q++) {
                float4 v = vr[q];
                acc[4 * q + 0] = fmaf(w, v.x, acc[4 * q + 0]);
                acc[4 * q + 1] = fmaf(w, v.y, acc[4 * q + 1]);
                acc[4 * q + 2] = fmaf(w, v.z, acc[4 * q + 2]);
                acc[4 * q + 3] = fmaf(w, v.w, acc[4 * q + 3]);
            }
        }
    }

    const float invs = 1.0f / s;
    float4* y4 = (float4*)(g_y + (size_t)p * YSTR);

    // Write feats first (shortens acc live range)
    #pragma unroll
    for (int q = 0; q < 16; q++)
        y4[9 + q] = make_float4(acc[4 * q + 0] * invs, acc[4 * q + 1] * invs,
                                acc[4 * q + 2] * invs, acc[4 * q + 3] * invs);

    // Positional encoding (accurate sincosf; args up to ~100.5)
    float pe[36];
    const float freqs[6] = {3.14159274101257324f,  6.28318548202514648f,
                            12.5663709640502930f,  25.1327419281005859f,
                            50.2654838562011719f,  100.530967712402344f};
    const float xv[3] = {x0, x1, x2};
    #pragma unroll
    for (int d = 0; d < 3; d++) {
        #pragma unroll
        for (int l = 0; l < 6; l++) {
            float sv, cv;
            sincosf(xv[d] * freqs[l], &sv, &cv);
            pe[d * 12 + l]     = sv;
            pe[d * 12 + 6 + l] = cv;
        }
    }
    #pragma unroll
    for (int q = 0; q < 9; q++)
        y4[q] = make_float4(pe[4 * q], pe[4 * q + 1], pe[4 * q + 2], pe[4 * q + 3]);
}

// ---------------------------------------------------------------------------
// Kernel 2: 4x hidden MLP + output layer. Block = 64 points, 256 threads.
// Per-thread tile: 4 points x 8 outputs. Weights staged in split-K chunks of
// 64 rows so total smem = 3 x 64 x WS x 4B = 101376B -> 2 blocks/SM.
// ---------------------------------------------------------------------------
__device__ __forceinline__ float snake(float h)
{
    float sv = __sinf(h);
    return fmaf(0.5f, h, sv * sv);
}

template <int K>
__device__ __forceinline__ void mlp_layer(
    const float* __restrict__ Ain, float* __restrict__ Bout, float* __restrict__ Wsh,
    const float* __restrict__ Wg, const float* __restrict__ bg,
    int tid, int tx, int ty)
{
    float4 blo = ((const float4*)bg)[tx];
    float4 bhi = ((const float4*)(bg + 64))[tx];
    float acc[4][8];
    #pragma unroll
    for (int pp = 0; pp < 4; pp++) {
        acc[pp][0] = blo.x; acc[pp][1] = blo.y; acc[pp][2] = blo.z; acc[pp][3] = blo.w;
        acc[pp][4] = bhi.x; acc[pp][5] = bhi.y; acc[pp][6] = bhi.z; acc[pp][7] = bhi.w;
    }

    #pragma unroll
    for (int k0 = 0; k0 < K; k0 += 64) {
        const int KC = (K - k0 < 64) ? (K - k0) : 64;
        __syncthreads();   // prior consumers of Wsh / producers of Ain done
        // Stage transposed weight chunk: Wsh[kk][j] = Wg[j][k0+kk]
        for (int i = tid; i < HID * KC; i += 256) {
            int j  = i / KC;
            int kk = i - j * KC;
            Wsh[kk * WS + j] = Wg[j * K + k0 + kk];
        }
        __syncthreads();

        for (int kq = 0; kq < KC; kq += 4) {
            float4 a4[4];
            #pragma unroll
            for (int pp = 0; pp < 4; pp++)
                a4[pp] = *(const float4*)(Ain + (4 * ty + pp) * WS + k0 + kq);
            #pragma unroll
            for (int dk = 0; dk < 4; dk++) {
                float4 wlo = *(const float4*)(Wsh + (kq + dk) * WS + 4 * tx);
                float4 whi = *(const float4*)(Wsh + (kq + dk) * WS + 64 + 4 * tx);
                #pragma unroll
                for (int pp = 0; pp < 4; pp++) {
                    float a = ((const float*)&a4[pp])[dk];
                    acc[pp][0] = fmaf(a, wlo.x, acc[pp][0]);
                    acc[pp][1] = fmaf(a, wlo.y, acc[pp][1]);
                    acc[pp][2] = fmaf(a, wlo.z, acc[pp][2]);
                    acc[pp][3] = fmaf(a, wlo.w, acc[pp][3]);
                    acc[pp][4] = fmaf(a, whi.x, acc[pp][4]);
                    acc[pp][5] = fmaf(a, whi.y, acc[pp][5]);
                    acc[pp][6] = fmaf(a, whi.z, acc[pp][6]);
                    acc[pp][7] = fmaf(a, whi.w, acc[pp][7]);
                }
            }
        }
    }
    __syncthreads();  // Bout may alias a buffer others still read

    #pragma unroll
    for (int pp = 0; pp < 4; pp++) {
        float r[8];
        #pragma unroll
        for (int o = 0; o < 8; o++) r[o] = snake(acc[pp][o]);
        *(float4*)(Bout + (4 * ty + pp) * WS + 4 * tx)      = make_float4(r[0], r[1], r[2], r[3]);
        *(float4*)(Bout + (4 * ty + pp) * WS + 64 + 4 * tx) = make_float4(r[4], r[5], r[6], r[7]);
    }
}

__global__ void __launch_bounds__(256, 2) mlp_kernel(
    const float* __restrict__ W0, const float* __restrict__ b0,
    const float* __restrict__ W1, const float* __restrict__ b1,
    const float* __restrict__ W2, const float* __restrict__ b2,
    const float* __restrict__ W3, const float* __restrict__ b3,
    const float* __restrict__ W4, const float* __restrict__ b4,
    float* __restrict__ out)
{
    extern __shared__ float sm[];
    float* A   = sm;                 // [64][WS]
    float* B   = A + 64 * WS;        // [64][WS]
    float* Wsh = B + 64 * WS;        // [64][WS] split-K weight chunk

    const int tid = threadIdx.x;
    const int tx  = tid & 15;
    const int ty  = tid >> 4;
    const int p0  = blockIdx.x * 64;

    // Load 64 input rows (100 valid cols; pad cols never consumed)
    const float* yb = g_y + (size_t)p0 * YSTR;
    for (int i = tid; i < 64 * 26; i += 256) {
        int r = i / 26;
        int c = i - r * 26;
        ((float4*)(A + r * WS))[c] = ((const float4*)(yb + (size_t)r * YSTR))[c];
    }

    mlp_layer<100>(A, B, Wsh, W0, b0, tid, tx, ty);
    mlp_layer<128>(B, A, Wsh, W1, b1, tid, tx, ty);
    mlp_layer<128>(A, B, Wsh, W2, b2, tid, tx, ty);
    mlp_layer<128>(B, A, Wsh, W3, b3, tid, tx, ty);
    __syncthreads();

    // Output layer: 64 points x dot(128)
    if (tid < 64) {
        const float* h = A + tid * WS;
        float sum = 0.0f;
        #pragma unroll 8
        for (int i = 0; i < 128; i++) sum = fmaf(h[i], __ldg(W4 + i), sum);
        out[p0 + tid] = sum + __ldg(b4);
    }
}

// ---------------------------------------------------------------------------
extern "C" void kernel_launch(void* const* d_in, const int* in_sizes, int n_in,
                              void* d_out, int out_size)
{
    const float* x  = (const float*)d_in[0];
    const float* fl = (const float*)d_in[1];
    const float* fv = (const float*)d_in[2];
    const float* W0 = (const float*)d_in[3];
    const float* b0 = (const float*)d_in[4];
    const float* W1 = (const float*)d_in[5];
    const float* b1 = (const float*)d_in[6];
    const float* W2 = (const float*)d_in[7];
    const float* b2 = (const float*)d_in[8];
    const float* W3 = (const float*)d_in[9];
    const float* b3 = (const float*)d_in[10];
    const float* W4 = (const float*)d_in[11];
    const float* b4 = (const float*)d_in[12];
    float* out = (float*)d_out;

    const size_t sm1 = (size_t)(4 * N_FEATS + CF * FDIM) * sizeof(float);   // 80000 B
    const size_t sm2 = (size_t)(3 * 64 * WS) * sizeof(float);               // 101376 B

    cudaFuncSetAttribute(attn_kernel, cudaFuncAttributeMaxDynamicSharedMemorySize, (int)sm1);
    cudaFuncSetAttribute(mlp_kernel,  cudaFuncAttributeMaxDynamicSharedMemorySize, (int)sm2);

    attn_kernel<<<N_PTS / 256, 256, sm1>>>(x, fl, fv);
    mlp_kernel<<<N_PTS / 64, 256, sm2>>>(W0, b0, W1, b1, W2, b2, W3, b3, W4, b4, out);
}

// round 11
// speedup vs baseline: 1.0018x; 1.0018x over previous
#include <cuda_runtime.h>
#include <math.h>

#define N_PTS   131072
#define N_FEATS 1000
#define FDIM    64
#define YSTR    104        // padded scratch row stride (100 valid + 4 pad)
#define CF      250        // feature-vector chunk rows staged in smem (80KB total -> 2 blocks/SM)
#define HID     128
#define WS      132        // smem row stride (words), conflict-free float4 reads

// Scratch for [PE(36) | feats(64)] rows. __device__ global (no runtime alloc).
__device__ __align__(16) float g_y[(size_t)N_PTS * YSTR];

// ---------------------------------------------------------------------------
// Kernel 1: distance softmax over 1000 features + weighted feature gather + PE
// ---------------------------------------------------------------------------
__global__ void __launch_bounds__(256, 2) attn_kernel(
    const float* __restrict__ x,
    const float* __restrict__ floc,
    const float* __restrict__ fvec)
{
    extern __shared__ float sm[];
    float* Mx = sm;                   // [1000] = -2*loc.x
    float* My = sm + N_FEATS;         // [1000] = -2*loc.y
    float* Mz = sm + 2 * N_FEATS;     // [1000] = -2*loc.z
    float* Nn = sm + 3 * N_FEATS;     // [1000] = |loc|^2
    float* Vs = sm + 4 * N_FEATS;     // [CF*64]

    const int tid = threadIdx.x;
    const int p   = blockIdx.x * 256 + tid;

    // Stage locations (pre-scaled) + norms
    for (int i = tid; i < N_FEATS; i += 256) {
        float a = floc[3 * i + 0];
        float b = floc[3 * i + 1];
        float c = floc[3 * i + 2];
        Mx[i] = -2.0f * a; My[i] = -2.0f * b; Mz[i] = -2.0f * c;
        Nn[i] = a * a + b * b + c * c;
    }
    __syncthreads();

    const float x0 = x[3 * p + 0];
    const float x1 = x[3 * p + 1];
    const float x2 = x[3 * p + 2];
    const float xx = x0 * x0 + x1 * x1 + x2 * x2;

    // Pass 1: max of inv_d. inv = clamp(rsqrt(d2), 1e6) == 1/(sqrt(d2)+1e-6)
    // to within 1e-5 rel for any d2 of nonzero measure.
    float m = -1e30f;
    #pragma unroll 4
    for (int f = 0; f < N_FEATS; f++) {
        float d2 = fmaf(x2, Mz[f], fmaf(x1, My[f], fmaf(x0, Mx[f], xx + Nn[f])));
        d2 = fmaxf(d2, 0.0f);
        float inv = fminf(rsqrtf(d2), 1e6f);
        m = fmaxf(m, inv);
    }

    // Pass 2: exp weights + weighted V accumulation (64 regs)
    float s = 0.0f;
    float acc[FDIM];
    #pragma unroll
    for (int j = 0; j < FDIM; j++) acc[j] = 0.0f;

    for (int ch = 0; ch < N_FEATS / CF; ch++) {
        __syncthreads();
        const float4* src = (const float4*)(fvec + (size_t)ch * CF * FDIM);
        float4*       dst = (float4*)Vs;
        for (int i = tid; i < CF * FDIM / 4; i += 256) dst[i] = src[i];
        __syncthreads();

        const int base = ch * CF;
        #pragma unroll 1
        for (int f = 0; f < CF; f++) {
            const int g = base + f;
            float d2 = fmaf(x2, Mz[g], fmaf(x1, My[g], fmaf(x0, Mx[g], xx + Nn[g])));
            d2 = fmaxf(d2, 0.0f);
            float inv = fminf(rsqrtf(d2), 1e6f);
            float w = __expf(inv - m);
            s += w;
            const float4* vr = (const float4*)(Vs + f * FDIM);  // warp-broadcast
            #pragma unroll
            for (int q = 0; q < 16; q++) {
                float4 v = vr[q];
                acc[4 * q + 0] = fmaf(w, v.x, acc[4 * q + 0]);
                acc[4 * q + 1] = fmaf(w, v.y, acc[4 * q + 1]);
                acc[4 * q + 2] = fmaf(w, v.z, acc[4 * q + 2]);
                acc[4 * q + 3] = fmaf(w, v.w, acc[4 * q + 3]);
            }
        }
    }

    const float invs = 1.0f / s;
    float4* y4 = (float4*)(g_y + (size_t)p * YSTR);

    // Write feats first (shortens acc live range)
    #pragma unroll
    for (int q = 0; q < 16; q++)
        y4[9 + q] = make_float4(acc[4 * q + 0] * invs, acc[4 * q + 1] * invs,
                                acc[4 * q + 2] * invs, acc[4 * q + 3] * invs);

    // Positional encoding (accurate sincosf; args up to ~100.5)
    float pe[36];
    const float freqs[6] = {3.14159274101257324f,  6.28318548202514648f,
                            12.5663709640502930f,  25.1327419281005859f,
                            50.2654838562011719f,  100.530967712402344f};
    const float xv[3] = {x0, x1, x2};
    #pragma unroll
    for (int d = 0; d < 3; d++) {
        #pragma unroll
        for (int l = 0; l < 6; l++) {
            float sv, cv;
            sincosf(xv[d] * freqs[l], &sv, &cv);
            pe[d * 12 + l]     = sv;
            pe[d * 12 + 6 + l] = cv;
        }
    }
    #pragma unroll
    for (int q = 0; q < 9; q++)
        y4[q] = make_float4(pe[4 * q], pe[4 * q + 1], pe[4 * q + 2], pe[4 * q + 3]);
}

// ---------------------------------------------------------------------------
// Kernel 2: 4x hidden MLP + output layer. Block = 64 points, 256 threads.
// Per-thread tile: 4 points x 8 outputs. Weights staged in split-K chunks of
// 64 rows so total smem = 3 x 64 x WS x 4B = 101376B -> 2 blocks/SM.
// ---------------------------------------------------------------------------
__device__ __forceinline__ float snake(float h)
{
    float sv = __sinf(h);
    return fmaf(0.5f, h, sv * sv);
}

template <int K>
__device__ __forceinline__ void mlp_layer(
    const float* __restrict__ Ain, float* __restrict__ Bout, float* __restrict__ Wsh,
    const float* __restrict__ Wg, const float* __restrict__ bg,
    int tid, int tx, int ty)
{
    float4 blo = ((const float4*)bg)[tx];
    float4 bhi = ((const float4*)(bg + 64))[tx];
    float acc[4][8];
    #pragma unroll
    for (int pp = 0; pp < 4; pp++) {
        acc[pp][0] = blo.x; acc[pp][1] = blo.y; acc[pp][2] = blo.z; acc[pp][3] = blo.w;
        acc[pp][4] = bhi.x; acc[pp][5] = bhi.y; acc[pp][6] = bhi.z; acc[pp][7] = bhi.w;
    }

    #pragma unroll
    for (int k0 = 0; k0 < K; k0 += 64) {
        const int KC = (K - k0 < 64) ? (K - k0) : 64;
        __syncthreads();   // prior consumers of Wsh / producers of Ain done
        // Stage transposed weight chunk: Wsh[kk][j] = Wg[j][k0+kk]
        for (int i = tid; i < HID * KC; i += 256) {
            int j  = i / KC;
            int kk = i - j * KC;
            Wsh[kk * WS + j] = Wg[j * K + k0 + kk];
        }
        __syncthreads();

        for (int kq = 0; kq < KC; kq += 4) {
            float4 a4[4];
            #pragma unroll
            for (int pp = 0; pp < 4; pp++)
                a4[pp] = *(const float4*)(Ain + (4 * ty + pp) * WS + k0 + kq);
            #pragma unroll
            for (int dk = 0; dk < 4; dk++) {
                float4 wlo = *(const float4*)(Wsh + (kq + dk) * WS + 4 * tx);
                float4 whi = *(const float4*)(Wsh + (kq + dk) * WS + 64 + 4 * tx);
                #pragma unroll
                for (int pp = 0; pp < 4; pp++) {
                    float a = ((const float*)&a4[pp])[dk];
                    acc[pp][0] = fmaf(a, wlo.x, acc[pp][0]);
                    acc[pp][1] = fmaf(a, wlo.y, acc[pp][1]);
                    acc[pp][2] = fmaf(a, wlo.z, acc[pp][2]);
                    acc[pp][3] = fmaf(a, wlo.w, acc[pp][3]);
                    acc[pp][4] = fmaf(a, whi.x, acc[pp][4]);
                    acc[pp][5] = fmaf(a, whi.y, acc[pp][5]);
                    acc[pp][6] = fmaf(a, whi.z, acc[pp][6]);
                    acc[pp][7] = fmaf(a, whi.w, acc[pp][7]);
                }
            }
        }
    }
    __syncthreads();  // Bout may alias a buffer others still read

    #pragma unroll
    for (int pp = 0; pp < 4; pp++) {
        float r[8];
        #pragma unroll
        for (int o = 0; o < 8; o++) r[o] = snake(acc[pp][o]);
        *(float4*)(Bout + (4 * ty + pp) * WS + 4 * tx)      = make_float4(r[0], r[1], r[2], r[3]);
        *(float4*)(Bout + (4 * ty + pp) * WS + 64 + 4 * tx) = make_float4(r[4], r[5], r[6], r[7]);
    }
}

__global__ void __launch_bounds__(256, 2) mlp_kernel(
    const float* __restrict__ W0, const float* __restrict__ b0,
    const float* __restrict__ W1, const float* __restrict__ b1,
    const float* __restrict__ W2, const float* __restrict__ b2,
    const float* __restrict__ W3, const float* __restrict__ b3,
    const float* __restrict__ W4, const float* __restrict__ b4,
    float* __restrict__ out)
{
    extern __shared__ float sm[];
    float* A   = sm;                 // [64][WS]
    float* B   = A + 64 * WS;        // [64][WS]
    float* Wsh = B + 64 * WS;        // [64][WS] split-K weight chunk

    const int tid = threadIdx.x;
    const int tx  = tid & 15;
    const int ty  = tid >> 4;
    const int p0  = blockIdx.x * 64;

    // Load 64 input rows (100 valid cols; pad cols never consumed)
    const float* yb = g_y + (size_t)p0 * YSTR;
    for (int i = tid; i < 64 * 26; i += 256) {
        int r = i / 26;
        int c = i - r * 26;
        ((float4*)(A + r * WS))[c] = ((const float4*)(yb + (size_t)r * YSTR))[c];
    }

    mlp_layer<100>(A, B, Wsh, W0, b0, tid, tx, ty);
    mlp_layer<128>(B, A, Wsh, W1, b1, tid, tx, ty);
    mlp_layer<128>(A, B, Wsh, W2, b2, tid, tx, ty);
    mlp_layer<128>(B, A, Wsh, W3, b3, tid, tx, ty);
    __syncthreads();

    // Output layer: 64 points x dot(128)
    if (tid < 64) {
        const float* h = A + tid * WS;
        float sum = 0.0f;
        #pragma unroll 8
        for (int i = 0; i < 128; i++) sum = fmaf(h[i], __ldg(W4 + i), sum);
        out[p0 + tid] = sum + __ldg(b4);
    }
}

// ---------------------------------------------------------------------------
extern "C" void kernel_launch(void* const* d_in, const int* in_sizes, int n_in,
                              void* d_out, int out_size)
{
    const float* x  = (const float*)d_in[0];
    const float* fl = (const float*)d_in[1];
    const float* fv = (const float*)d_in[2];
    const float* W0 = (const float*)d_in[3];
    const float* b0 = (const float*)d_in[4];
    const float* W1 = (const float*)d_in[5];
    const float* b1 = (const float*)d_in[6];
    const float* W2 = (const float*)d_in[7];
    const float* b2 = (const float*)d_in[8];
    const float* W3 = (const float*)d_in[9];
    const float* b3 = (const float*)d_in[10];
    const float* W4 = (const float*)d_in[11];
    const float* b4 = (const float*)d_in[12];
    float* out = (float*)d_out;

    const size_t sm1 = (size_t)(4 * N_FEATS + CF * FDIM) * sizeof(float);   // 80000 B
    const size_t sm2 = (size_t)(3 * 64 * WS) * sizeof(float);               // 101376 B

    cudaFuncSetAttribute(attn_kernel, cudaFuncAttributeMaxDynamicSharedMemorySize, (int)sm1);
    cudaFuncSetAttribute(mlp_kernel,  cudaFuncAttributeMaxDynamicSharedMemorySize, (int)sm2);

    attn_kernel<<<N_PTS / 256, 256, sm1>>>(x, fl, fv);
    mlp_kernel<<<N_PTS / 64, 256, sm2>>>(W0, b0, W1, b1, W2, b2, W3, b3, W4, b4, out);
}

// round 14
// speedup vs baseline: 1.3735x; 1.3710x over previous
#include <cuda_runtime.h>
#include <cuda_bf16.h>
#include <math.h>
#include <stdint.h>

#define N_PTS   131072
#define N_FEATS 1000
#define FDIM    64
#define YSTR    104        // padded scratch row stride (100 valid + 4 zero pad)
#define CF      250
#define HID     128
#define AST     136        // bf16 row stride (17 x 16B units -> ldmatrix conflict-free)

// Scratch for [PE(36) | feats(64) | 0pad(4)] rows.
__device__ __align__(16) float g_y[(size_t)N_PTS * YSTR];
// Pre-converted weight images (smem layout: 128 rows x 136 bf16, zero-padded)
__device__ __align__(16) __nv_bfloat16 g_whi[4][128 * AST];
__device__ __align__(16) __nv_bfloat16 g_wlo[4][128 * AST];

__device__ __forceinline__ uint32_t smem_u32(const void* p) {
    uint32_t a;
    asm("{ .reg .u64 t; cvta.to.shared.u64 t, %1; cvt.u32.u64 %0, t; }" : "=r"(a) : "l"(p));
    return a;
}
__device__ __forceinline__ uint32_t pack_bf2(float a, float b) {
    __nv_bfloat162 t = __floats2bfloat162_rn(a, b);
    return *reinterpret_cast<uint32_t*>(&t);
}
__device__ __forceinline__ float snake(float h) {
    float sv = __sinf(h);
    return fmaf(0.5f, h, sv * sv);
}
__device__ __forceinline__ void ldm_x4(uint32_t& r0, uint32_t& r1, uint32_t& r2, uint32_t& r3,
                                       uint32_t addr) {
    asm volatile("ldmatrix.sync.aligned.m8n8.x4.shared.b16 {%0, %1, %2, %3}, [%4];"
                 : "=r"(r0), "=r"(r1), "=r"(r2), "=r"(r3) : "r"(addr));
}
__device__ __forceinline__ void mma_bf16(float* c, uint32_t a0, uint32_t a1, uint32_t a2,
                                         uint32_t a3, uint32_t b0, uint32_t b1) {
    asm volatile(
        "mma.sync.aligned.m16n8k16.row.col.f32.bf16.bf16.f32 "
        "{%0, %1, %2, %3}, {%4, %5, %6, %7}, {%8, %9}, {%0, %1, %2, %3};"
        : "+f"(c[0]), "+f"(c[1]), "+f"(c[2]), "+f"(c[3])
        : "r"(a0), "r"(a1), "r"(a2), "r"(a3), "r"(b0), "r"(b1));
}

// ---------------------------------------------------------------------------
// Kernel 0: convert W0..W3 (fp32) -> bf16 hi/lo smem-image layout in global.
// ---------------------------------------------------------------------------
__global__ void prep_kernel(const float* __restrict__ W0, const float* __restrict__ W1,
                            const float* __restrict__ W2, const float* __restrict__ W3)
{
    const int l = blockIdx.x;
    const float* W = (l == 0) ? W0 : (l == 1) ? W1 : (l == 2) ? W2 : W3;
    const int K = (l == 0) ? 100 : 128;
    for (int i = threadIdx.x; i < 128 * AST; i += 256) {
        int n = i / AST, k = i - n * AST;
        float w = (k < K) ? W[n * K + k] : 0.0f;
        __nv_bfloat16 wh = __float2bfloat16(w);
        g_whi[l][i] = wh;
        g_wlo[l][i] = __float2bfloat16(w - __bfloat162float(wh));
    }
}

// ---------------------------------------------------------------------------
// Kernel 1: distance softmax + weighted feature gather + PE
// ---------------------------------------------------------------------------
__global__ void __launch_bounds__(256, 2) attn_kernel(
    const float* __restrict__ x,
    const float* __restrict__ floc,
    const float* __restrict__ fvec)
{
    extern __shared__ float sm[];
    float* Mx = sm;
    float* My = sm + N_FEATS;
    float* Mz = sm + 2 * N_FEATS;
    float* Nn = sm + 3 * N_FEATS;
    float* Vs = sm + 4 * N_FEATS;

    const int tid = threadIdx.x;
    const int p   = blockIdx.x * 256 + tid;

    for (int i = tid; i < N_FEATS; i += 256) {
        float a = floc[3 * i + 0];
        float b = floc[3 * i + 1];
        float c = floc[3 * i + 2];
        Mx[i] = -2.0f * a; My[i] = -2.0f * b; Mz[i] = -2.0f * c;
        Nn[i] = a * a + b * b + c * c;
    }
    __syncthreads();

    const float x0 = x[3 * p + 0];
    const float x1 = x[3 * p + 1];
    const float x2 = x[3 * p + 2];
    const float xx = x0 * x0 + x1 * x1 + x2 * x2;

    float m = -1e30f;
    #pragma unroll 4
    for (int f = 0; f < N_FEATS; f++) {
        float d2 = fmaf(x2, Mz[f], fmaf(x1, My[f], fmaf(x0, Mx[f], xx + Nn[f])));
        d2 = fmaxf(d2, 0.0f);
        float inv = fminf(rsqrtf(d2), 1e6f);
        m = fmaxf(m, inv);
    }

    float s = 0.0f;
    float acc[FDIM];
    #pragma unroll
    for (int j = 0; j < FDIM; j++) acc[j] = 0.0f;

    for (int ch = 0; ch < N_FEATS / CF; ch++) {
        __syncthreads();
        const float4* src = (const float4*)(fvec + (size_t)ch * CF * FDIM);
        float4*       dst = (float4*)Vs;
        for (int i = tid; i < CF * FDIM / 4; i += 256) dst[i] = src[i];
        __syncthreads();

        const int base = ch * CF;
        #pragma unroll 1
        for (int f = 0; f < CF; f++) {
            const int g = base + f;
            float d2 = fmaf(x2, Mz[g], fmaf(x1, My[g], fmaf(x0, Mx[g], xx + Nn[g])));
            d2 = fmaxf(d2, 0.0f);
            float inv = fminf(rsqrtf(d2), 1e6f);
            float w = __expf(inv - m);
            s += w;
            const float4* vr = (const float4*)(Vs + f * FDIM);
            #pragma unroll
            for (int q = 0; q < 16; q++) {
                float4 v = vr[q];
                acc[4 * q + 0] = fmaf(w, v.x, acc[4 * q + 0]);
                acc[4 * q + 1] = fmaf(w, v.y, acc[4 * q + 1]);
                acc[4 * q + 2] = fmaf(w, v.z, acc[4 * q + 2]);
                acc[4 * q + 3] = fmaf(w, v.w, acc[4 * q + 3]);
            }
        }
    }

    const float invs = 1.0f / s;
    float4* y4 = (float4*)(g_y + (size_t)p * YSTR);

    #pragma unroll
    for (int q = 0; q < 16; q++)
        y4[9 + q] = make_float4(acc[4 * q + 0] * invs, acc[4 * q + 1] * invs,
                                acc[4 * q + 2] * invs, acc[4 * q + 3] * invs);
    y4[25] = make_float4(0.f, 0.f, 0.f, 0.f);   // zero pad cols 100..103

    float pe[36];
    const float freqs[6] = {3.14159274101257324f,  6.28318548202514648f,
                            12.5663709640502930f,  25.1327419281005859f,
                            50.2654838562011719f,  100.530967712402344f};
    const float xv[3] = {x0, x1, x2};
    #pragma unroll
    for (int d = 0; d < 3; d++) {
        #pragma unroll
        for (int l = 0; l < 6; l++) {
            float sv, cv;
            sincosf(xv[d] * freqs[l], &sv, &cv);
            pe[d * 12 + l]     = sv;
            pe[d * 12 + 6 + l] = cv;
        }
    }
    #pragma unroll
    for (int q = 0; q < 9; q++)
        y4[q] = make_float4(pe[4 * q], pe[4 * q + 1], pe[4 * q + 2], pe[4 * q + 3]);
}

// ---------------------------------------------------------------------------
// Kernel 2: warp-MMA bf16 (hi/lo 3-term) MLP. CTA = 128 points, 256 threads.
// SMEM: A_hi/A_lo [128][AST] bf16 (in-place across layers), W_hi/W_lo images,
// bias, W4. Warp w computes rows 16w..16w+15 x all 128 outputs (64 fp32 regs).
// ---------------------------------------------------------------------------
#define SO_AHI  0
#define SO_ALO  (128 * AST * 2)            // 34816
#define SO_WHI  (2 * 128 * AST * 2)        // 69632
#define SO_WLO  (3 * 128 * AST * 2)        // 104448
#define SO_BIAS (4 * 128 * AST * 2)        // 139264
#define SO_W4   (SO_BIAS + 512)
#define MLP_SMEM (SO_W4 + 512)             // 140288

__global__ void __launch_bounds__(256, 1) mlp_mma_kernel(
    const float* __restrict__ b0, const float* __restrict__ b1,
    const float* __restrict__ b2, const float* __restrict__ b3,
    const float* __restrict__ W4, const float* __restrict__ b4,
    float* __restrict__ out)
{
    extern __shared__ char smc[];
    const uint32_t sb = smem_u32(smc);
    float* bias = (float*)(smc + SO_BIAS);
    float* w4s  = (float*)(smc + SO_W4);

    const int tid  = threadIdx.x;
    const int wid  = tid >> 5;
    const int lane = tid & 31;
    const int qid  = lane >> 2;          // 0..7
    const int qtr  = lane & 3;           // 0..3
    const int p0   = blockIdx.x * 128;

    // ---- Prologue: stage A0 from g_y as bf16 hi/lo ----
    {
        const int row  = tid >> 1;
        const int cs   = (tid & 1) * 64;
        const float* yrow = g_y + (size_t)(p0 + row) * YSTR;
        char* ah = smc + SO_AHI + (row * AST + cs) * 2;
        char* al = smc + SO_ALO + (row * AST + cs) * 2;
        #pragma unroll
        for (int i = 0; i < 16; i++) {
            const int col = cs + 4 * i;
            float4 v = (col < YSTR) ? *(const float4*)(yrow + col)
                                    : make_float4(0.f, 0.f, 0.f, 0.f);
            uint32_t h0 = pack_bf2(v.x, v.y);
            uint32_t h1 = pack_bf2(v.z, v.w);
            __nv_bfloat162 hh0 = *reinterpret_cast<__nv_bfloat162*>(&h0);
            __nv_bfloat162 hh1 = *reinterpret_cast<__nv_bfloat162*>(&h1);
            uint32_t l0 = pack_bf2(v.x - __bfloat162float(hh0.x), v.y - __bfloat162float(hh0.y));
            uint32_t l1 = pack_bf2(v.z - __bfloat162float(hh1.x), v.w - __bfloat162float(hh1.y));
            *(uint32_t*)(ah + 8 * i)     = h0;
            *(uint32_t*)(ah + 8 * i + 4) = h1;
            *(uint32_t*)(al + 8 * i)     = l0;
            *(uint32_t*)(al + 8 * i + 4) = l1;
        }
    }

    // Per-lane ldmatrix base addresses
    const uint32_t a_base = sb + SO_AHI +
        (uint32_t)(((16 * wid + (lane & 15)) * AST + ((lane >> 4) << 3)) * 2);
    const uint32_t w_base = sb + SO_WHI +
        (uint32_t)((((lane & 7) + ((lane >> 4) << 3)) * AST + (((lane >> 3) & 1) << 3)) * 2);

    #pragma unroll 1
    for (int l = 0; l < 4; l++) {
        const float* bg = (l == 0) ? b0 : (l == 1) ? b1 : (l == 2) ? b2 : b3;

        __syncthreads();   // prev epilogue A-writes visible; prev W reads done
        // Stage W images (flat copy) + bias
        {
            const uint4* shi = (const uint4*)g_whi[l];
            const uint4* slo = (const uint4*)g_wlo[l];
            uint4* dhi = (uint4*)(smc + SO_WHI);
            uint4* dlo = (uint4*)(smc + SO_WLO);
            #pragma unroll
            for (int i = 0; i < 2176 / 256; i++) {   // 2176 uint4 per buffer
                dhi[tid + 256 * i] = shi[tid + 256 * i];
                dlo[tid + 256 * i] = slo[tid + 256 * i];
            }
            { int i = 2176 - 128; if (tid < 128) { dhi[tid + i] = shi[tid + i]; dlo[tid + i] = slo[tid + i]; } }
            if (tid < 128) bias[tid] = bg[tid];
            if (l == 3 && tid < 128) w4s[tid] = W4[tid];
        }
        __syncthreads();

        // ---- MMA phase: C[16 x 128] per warp, 3-term hi/lo ----
        float c[16][4];
        #pragma unroll
        for (int nt = 0; nt < 16; nt++)
            #pragma unroll
            for (int j = 0; j < 4; j++) c[nt][j] = 0.0f;

        #pragma unroll 2
        for (int kk = 0; kk < 8; kk++) {
            uint32_t ah0, ah1, ah2, ah3, al0, al1, al2, al3;
            ldm_x4(ah0, ah1, ah2, ah3, a_base + kk * 32);
            ldm_x4(al0, al1, al2, al3, a_base + (SO_ALO - SO_AHI) + kk * 32);
            #pragma unroll
            for (int np = 0; np < 8; np++) {
                const uint32_t wa = w_base + np * (16 * AST * 2) + kk * 32;
                uint32_t h00, h01, h10, h11, q00, q01, q10, q11;
                ldm_x4(h00, h01, h10, h11, wa);
                ldm_x4(q00, q01, q10, q11, wa + (SO_WLO - SO_WHI));
                mma_bf16(c[2 * np],     ah0, ah1, ah2, ah3, h00, h01);
                mma_bf16(c[2 * np + 1], ah0, ah1, ah2, ah3, h10, h11);
                mma_bf16(c[2 * np],     al0, al1, al2, al3, h00, h01);
                mma_bf16(c[2 * np + 1], al0, al1, al2, al3, h10, h11);
                mma_bf16(c[2 * np],     ah0, ah1, ah2, ah3, q00, q01);
                mma_bf16(c[2 * np + 1], ah0, ah1, ah2, ah3, q10, q11);
            }
        }
        __syncthreads();   // all A/W reads done before epilogue overwrites A

        if (l < 3) {
            // bias + snake -> repack hi/lo -> in-place A store
            const int r0 = 16 * wid + qid;
            #pragma unroll
            for (int nt = 0; nt < 16; nt++) {
                const int col = 8 * nt + 2 * qtr;
                const float bb0 = bias[col], bb1 = bias[col + 1];
                float v0 = snake(c[nt][0] + bb0);
                float v1 = snake(c[nt][1] + bb1);
                float v2 = snake(c[nt][2] + bb0);
                float v3 = snake(c[nt][3] + bb1);
                uint32_t h0 = pack_bf2(v0, v1);
                uint32_t h2 = pack_bf2(v2, v3);
                __nv_bfloat162 hh0 = *reinterpret_cast<__nv_bfloat162*>(&h0);
                __nv_bfloat162 hh2 = *reinterpret_cast<__nv_bfloat162*>(&h2);
                uint32_t l0 = pack_bf2(v0 - __bfloat162float(hh0.x), v1 - __bfloat162float(hh0.y));
                uint32_t l2 = pack_bf2(v2 - __bfloat162float(hh2.x), v3 - __bfloat162float(hh2.y));
                *(uint32_t*)(smc + SO_AHI + (r0 * AST + col) * 2)       = h0;
                *(uint32_t*)(smc + SO_AHI + ((r0 + 8) * AST + col) * 2) = h2;
                *(uint32_t*)(smc + SO_ALO + (r0 * AST + col) * 2)       = l0;
                *(uint32_t*)(smc + SO_ALO + ((r0 + 8) * AST + col) * 2) = l2;
            }
        } else {
            // Output layer fused: dot(snake(h + bias), W4), quad reduce
            float s0 = 0.0f, s1 = 0.0f;
            #pragma unroll
            for (int nt = 0; nt < 16; nt++) {
                const int col = 8 * nt + 2 * qtr;
                const float bb0 = bias[col], bb1 = bias[col + 1];
                const float w40 = w4s[col],  w41 = w4s[col + 1];
                s0 = fmaf(snake(c[nt][0] + bb0), w40, s0);
                s0 = fmaf(snake(c[nt][1] + bb1), w41, s0);
                s1 = fmaf(snake(c[nt][2] + bb0), w40, s1);
                s1 = fmaf(snake(c[nt][3] + bb1), w41, s1);
            }
            s0 += __shfl_xor_sync(0xFFFFFFFF, s0, 1);
            s0 += __shfl_xor_sync(0xFFFFFFFF, s0, 2);
            s1 += __shfl_xor_sync(0xFFFFFFFF, s1, 1);
            s1 += __shfl_xor_sync(0xFFFFFFFF, s1, 2);
            if (qtr == 0) {
                const float bb4 = __ldg(b4);
                const int r0 = 16 * wid + qid;
                out[p0 + r0]     = s0 + bb4;
                out[p0 + r0 + 8] = s1 + bb4;
            }
        }
    }
}

// ---------------------------------------------------------------------------
extern "C" void kernel_launch(void* const* d_in, const int* in_sizes, int n_in,
                              void* d_out, int out_size)
{
    const float* x  = (const float*)d_in[0];
    const float* fl = (const float*)d_in[1];
    const float* fv = (const float*)d_in[2];
    const float* W0 = (const float*)d_in[3];
    const float* b0 = (const float*)d_in[4];
    const float* W1 = (const float*)d_in[5];
    const float* b1 = (const float*)d_in[6];
    const float* W2 = (const float*)d_in[7];
    const float* b2 = (const float*)d_in[8];
    const float* W3 = (const float*)d_in[9];
    const float* b3 = (const float*)d_in[10];
    const float* W4 = (const float*)d_in[11];
    const float* b4 = (const float*)d_in[12];
    float* out = (float*)d_out;

    const size_t sm1 = (size_t)(4 * N_FEATS + CF * FDIM) * sizeof(float);   // 80000 B

    cudaFuncSetAttribute(attn_kernel,    cudaFuncAttributeMaxDynamicSharedMemorySize, (int)sm1);
    cudaFuncSetAttribute(mlp_mma_kernel, cudaFuncAttributeMaxDynamicSharedMemorySize, MLP_SMEM);

    prep_kernel<<<4, 256>>>(W0, W1, W2, W3);
    attn_kernel<<<N_PTS / 256, 256, sm1>>>(x, fl, fv);
    mlp_mma_kernel<<<N_PTS / 128, 256, MLP_SMEM>>>(b0, b1, b2, b3, W4, b4, out);
}